// round 9
// baseline (speedup 1.0000x reference)
#include <cuda_runtime.h>
#include <cstdint>
#include <math.h>

#define SDIM 2048
#define DDIM 64
#define QT 128
#define KT 64
#define NT 128

#define STR 68   // shared row stride (floats): ldsm 8-row groups hit 8 distinct bank-quads

// smem layout (floats):
//  sK [64][68]  : K tile, row-major [kv][d]
//  sVt[64][68]  : V transposed [d][kv]
//  sP [128][68] : Q staging (blk0 rows) then P
//  sQc[64][68]  : compact Q rows for blk1 (global rows wid*32+16..31 -> compact wid*16+0..15)
#define OFF_K  0
#define OFF_VT (KT*STR)                   // 4352
#define OFF_P  (OFF_VT + DDIM*STR)        // 8704
#define OFF_QC (OFF_P + QT*STR)           // 17408
#define SMEM_FLOATS (OFF_QC + 64*STR)     // 21760
#define SMEM_BYTES  (SMEM_FLOATS*4)       // 87040

__device__ __forceinline__ float tf32r(float x){
    float y; asm("cvt.rna.tf32.f32 %0, %1;" : "=f"(y) : "f"(x)); return y;
}
__device__ __forceinline__ float ex2f(float x){
    float y; asm("ex2.approx.ftz.f32 %0, %1;" : "=f"(y) : "f"(x)); return y;
}
__device__ __forceinline__ uint32_t smem_u32(const void* p){
    uint32_t a;
    asm("{ .reg .u64 t; cvta.to.shared.u64 t, %1; cvt.u32.u64 %0, t; }":"=r"(a):"l"(p));
    return a;
}
__device__ __forceinline__ void mma8(float* d, const float* a, float b0, float b1){
    asm volatile("mma.sync.aligned.m16n8k8.row.col.f32.tf32.tf32.f32 "
                 "{%0,%1,%2,%3},{%4,%5,%6,%7},{%8,%9},{%0,%1,%2,%3};"
                 : "+f"(d[0]),"+f"(d[1]),"+f"(d[2]),"+f"(d[3])
                 : "f"(a[0]),"f"(a[1]),"f"(a[2]),"f"(a[3]),"f"(b0),"f"(b1));
}
__device__ __forceinline__ void ldsm4(uint32_t addr, uint32_t* r){
    asm volatile("ldmatrix.sync.aligned.m8n8.x4.shared.b16 {%0,%1,%2,%3}, [%4];"
                 : "=r"(r[0]),"=r"(r[1]),"=r"(r[2]),"=r"(r[3]) : "r"(addr));
}

__global__ void __launch_bounds__(NT, 2)
fa_mma(const float* __restrict__ qg_, const float* __restrict__ kg_,
       const float* __restrict__ vg_, float* __restrict__ og_)
{
    extern __shared__ float sm[];
    float* sK  = sm + OFF_K;
    float* sVt = sm + OFF_VT;
    float* sP  = sm + OFF_P;
    float* sQc = sm + OFF_QC;
    const uint32_t sb = smem_u32(sm);

    const int tid  = threadIdx.x;
    const int wid  = tid >> 5;
    const int lane = tid & 31;
    const int g    = lane >> 2;
    const int q    = lane & 3;
    const int wbase = wid * 32;      // warp owns q-rows [wbase, wbase+32)

    const int bh = blockIdx.y;
    const int qt = blockIdx.x;
    const size_t base = (size_t)bh * SDIM * DDIM;
    const float* qg = qg_ + base + (size_t)qt * QT * DDIM;
    const float* kg = kg_ + base;
    const float* vg = vg_ + base;
    float*       og = og_ + base + (size_t)qt * QT * DDIM;

    // ---- stage Q: blk0 rows -> sP (full-row addressing), blk1 rows -> sQc compact ----
    const float qs = 0.125f * 1.44269504088896340736f;
    for (int i = tid; i < QT * DDIM / 4; i += NT) {
        int row = i >> 4, c4 = i & 15;
        float4 a = ((const float4*)qg)[i];
        a.x = tf32r(a.x * qs); a.y = tf32r(a.y * qs);
        a.z = tf32r(a.z * qs); a.w = tf32r(a.w * qs);
        if (((row >> 4) & 1) == 0) {
            *(float4*)&sP[row * STR + c4 * 4] = a;          // blk0 rows
        } else {
            int cr = (row >> 5) * 16 + (row & 15);           // compact blk1 row
            *(float4*)&sQc[cr * STR + c4 * 4] = a;
        }
    }
    __syncthreads();

    // ---- Q blk0 fragments -> registers (persist) ----
    float qf[8][4];
    #pragma unroll
    for (int kb = 0; kb < 8; ++kb) {
        const int r0 = wbase + g;
        qf[kb][0] = sP[(r0    ) * STR + kb*8 + q    ];
        qf[kb][1] = sP[(r0 + 8) * STR + kb*8 + q    ];
        qf[kb][2] = sP[(r0    ) * STR + kb*8 + q + 4];
        qf[kb][3] = sP[(r0 + 8) * STR + kb*8 + q + 4];
    }
    __syncthreads();

    float o[2][8][4];
    #pragma unroll
    for (int blk = 0; blk < 2; ++blk)
        #pragma unroll
        for (int nb = 0; nb < 8; ++nb)
            { o[blk][nb][0]=0.f; o[blk][nb][1]=0.f; o[blk][nb][2]=0.f; o[blk][nb][3]=0.f; }
    float mx[2][2] = {{-INFINITY,-INFINITY},{-INFINITY,-INFINITY}};
    float lx[2][2] = {{0.f,0.f},{0.f,0.f}};

    // ---- per-lane LDSM base addresses ----
    // B-frag pattern (K, Vt): x4 = {nb_even kh0, nb_even kh1, nb_odd kh0, nb_odd kh1}
    const int b_nrow = ((lane >> 4) << 3) + (lane & 7);
    const int b_kh   = ((lane >> 3) & 1) << 2;
    const uint32_t aKb = sb + (uint32_t)((OFF_K  + b_nrow * STR + b_kh) * 4);
    const uint32_t aVb = sb + (uint32_t)((OFF_VT + b_nrow * STR + b_kh) * 4);
    // A-frag pattern (P, Qc): x4 = {rows0-7 kh0, rows8-15 kh0, rows0-7 kh1, rows8-15 kh1}
    const int pa_row = (((lane >> 3) & 1) << 3) + (lane & 7);
    const int pa_kh  = (lane >> 4) << 2;
    const uint32_t aPb = sb + (uint32_t)((OFF_P  + (wbase + pa_row) * STR + pa_kh) * 4);
    const uint32_t aQc = sb + (uint32_t)((OFF_QC + (wid*16 + pa_row) * STR + pa_kh) * 4);

    // V staging mapping: lanes sweep d (coalesced LDG.32), transpose into sVt
    const int v_dlo = lane;
    const int v_kv0 = wid * 4;

    for (int j = 0; j < SDIM / KT; ++j) {
        __syncthreads();   // prior tile's sK/sVt reads complete
        {
            const float4* kp = (const float4*)(kg + (size_t)j * KT * DDIM);
            #pragma unroll
            for (int it = 0; it < 8; ++it) {
                int i = tid + it * NT;
                int row = i >> 4, c4 = i & 15;
                float4 kv = kp[i];
                kv.x = tf32r(kv.x); kv.y = tf32r(kv.y); kv.z = tf32r(kv.z); kv.w = tf32r(kv.w);
                *(float4*)&sK[row * STR + c4 * 4] = kv;
            }
            const float* vt = vg + (size_t)j * KT * DDIM;
            #pragma unroll
            for (int h = 0; h < 2; ++h) {
                const int d = v_dlo + 32 * h;
                #pragma unroll
                for (int jj = 0; jj < 4; ++jj) {
                    const int kv0 = v_kv0 + 16 * jj;
                    float4 w;
                    w.x = tf32r(vt[(size_t)(kv0 + 0) * DDIM + d]);
                    w.y = tf32r(vt[(size_t)(kv0 + 1) * DDIM + d]);
                    w.z = tf32r(vt[(size_t)(kv0 + 2) * DDIM + d]);
                    w.w = tf32r(vt[(size_t)(kv0 + 3) * DDIM + d]);
                    *(float4*)&sVt[d * STR + kv0] = w;
                }
            }
        }
        __syncthreads();

        // ---- S = Q@K^T for BOTH blks: K frag loaded once, feeds 4 MMAs ----
        float c0[8][4], c1[8][4];
        #pragma unroll
        for (int nb = 0; nb < 8; ++nb) {
            c0[nb][0]=0.f; c0[nb][1]=0.f; c0[nb][2]=0.f; c0[nb][3]=0.f;
            c1[nb][0]=0.f; c1[nb][1]=0.f; c1[nb][2]=0.f; c1[nb][3]=0.f;
        }
        #pragma unroll
        for (int kb = 0; kb < 8; ++kb) {
            uint32_t qu[4];
            ldsm4(aQc + (uint32_t)(kb * 32), qu);          // blk1 Q frag
            float qa[4];
            #pragma unroll
            for (int t = 0; t < 4; ++t) qa[t] = __uint_as_float(qu[t]);
            #pragma unroll
            for (int p = 0; p < 4; ++p) {
                uint32_t r[4];
                ldsm4(aKb + (uint32_t)(((p*16) * STR + kb*8) * 4), r);
                const float b0 = __uint_as_float(r[0]);
                const float b1 = __uint_as_float(r[1]);
                const float b2 = __uint_as_float(r[2]);
                const float b3 = __uint_as_float(r[3]);
                mma8(c0[2*p  ], qf[kb], b0, b1);
                mma8(c0[2*p+1], qf[kb], b2, b3);
                mma8(c1[2*p  ], qa,     b0, b1);
                mma8(c1[2*p+1], qa,     b2, b3);
            }
        }

        // ---- online softmax per blk (blk0 on c0, blk1 on c1) ----
        #pragma unroll
        for (int blk = 0; blk < 2; ++blk) {
            float (*c)[4] = blk ? c1 : c0;
            float mtA = -INFINITY, mtB = -INFINITY;
            #pragma unroll
            for (int nb = 0; nb < 8; ++nb) {
                mtA = fmaxf(mtA, fmaxf(c[nb][0], c[nb][1]));
                mtB = fmaxf(mtB, fmaxf(c[nb][2], c[nb][3]));
            }
            mtA = fmaxf(mtA, __shfl_xor_sync(0xffffffffu, mtA, 1));
            mtA = fmaxf(mtA, __shfl_xor_sync(0xffffffffu, mtA, 2));
            mtB = fmaxf(mtB, __shfl_xor_sync(0xffffffffu, mtB, 1));
            mtB = fmaxf(mtB, __shfl_xor_sync(0xffffffffu, mtB, 2));
            const float mnA = fmaxf(mx[blk][0], mtA);
            const float mnB = fmaxf(mx[blk][1], mtB);
            const float aA  = ex2f(mx[blk][0] - mnA);
            const float aB  = ex2f(mx[blk][1] - mnB);
            float lsA = 0.f, lsB = 0.f;
            const int rA = wbase + blk * 16 + g;
            #pragma unroll
            for (int nb = 0; nb < 8; ++nb) {
                float p0 = ex2f(c[nb][0] - mnA);
                float p1 = ex2f(c[nb][1] - mnA);
                float p2 = ex2f(c[nb][2] - mnB);
                float p3 = ex2f(c[nb][3] - mnB);
                lsA += p0 + p1; lsB += p2 + p3;
                float2 fa; fa.x = tf32r(p0); fa.y = tf32r(p1);
                float2 fb; fb.x = tf32r(p2); fb.y = tf32r(p3);
                *(float2*)&sP[(rA    ) * STR + nb*8 + 2*q] = fa;
                *(float2*)&sP[(rA + 8) * STR + nb*8 + 2*q] = fb;
            }
            lsA += __shfl_xor_sync(0xffffffffu, lsA, 1);
            lsA += __shfl_xor_sync(0xffffffffu, lsA, 2);
            lsB += __shfl_xor_sync(0xffffffffu, lsB, 1);
            lsB += __shfl_xor_sync(0xffffffffu, lsB, 2);
            mx[blk][0] = mnA; mx[blk][1] = mnB;
            lx[blk][0] = lx[blk][0] * aA + lsA;
            lx[blk][1] = lx[blk][1] * aB + lsB;
            #pragma unroll
            for (int nb = 0; nb < 8; ++nb) {
                o[blk][nb][0] *= aA; o[blk][nb][1] *= aA;
                o[blk][nb][2] *= aB; o[blk][nb][3] *= aB;
            }
        }
        __syncwarp();   // P stores visible to all lanes before LDSM reads

        // ---- O += P @ V : A via LDSM from sP, B via LDSM from sVt ----
        #pragma unroll
        for (int kb = 0; kb < 8; ++kb) {
            uint32_t u0[4], u1[4];
            ldsm4(aPb + (uint32_t)((kb*8) * 4), u0);
            ldsm4(aPb + (uint32_t)((16 * STR + kb*8) * 4), u1);
            float a0[4], a1[4];
            #pragma unroll
            for (int t = 0; t < 4; ++t) { a0[t] = __uint_as_float(u0[t]); a1[t] = __uint_as_float(u1[t]); }
            #pragma unroll
            for (int p = 0; p < 4; ++p) {
                uint32_t rv[4];
                ldsm4(aVb + (uint32_t)(((p*16) * STR + kb*8) * 4), rv);
                const float b0 = __uint_as_float(rv[0]);
                const float b1 = __uint_as_float(rv[1]);
                const float b2 = __uint_as_float(rv[2]);
                const float b3 = __uint_as_float(rv[3]);
                mma8(o[0][2*p  ], a0, b0, b1);
                mma8(o[0][2*p+1], a0, b2, b3);
                mma8(o[1][2*p  ], a1, b0, b1);
                mma8(o[1][2*p+1], a1, b2, b3);
            }
        }
        __syncwarp();   // PV reads of sP done before next tile's softmax overwrites
    }

    // ---- epilogue: normalize, store ----
    #pragma unroll
    for (int blk = 0; blk < 2; ++blk) {
        const float invA = 1.0f / lx[blk][0];
        const float invB = 1.0f / lx[blk][1];
        const int rA = wbase + blk * 16 + g;
        #pragma unroll
        for (int nb = 0; nb < 8; ++nb) {
            float2 sa; sa.x = o[blk][nb][0] * invA; sa.y = o[blk][nb][1] * invA;
            float2 sb2; sb2.x = o[blk][nb][2] * invB; sb2.y = o[blk][nb][3] * invB;
            *(float2*)&og[(size_t)(rA    ) * DDIM + nb*8 + 2*q] = sa;
            *(float2*)&og[(size_t)(rA + 8) * DDIM + nb*8 + 2*q] = sb2;
        }
    }
}

extern "C" void kernel_launch(void* const* d_in, const int* in_sizes, int n_in,
                              void* d_out, int out_size)
{
    const float* q = (const float*)d_in[0];
    const float* k = (const float*)d_in[1];
    const float* v = (const float*)d_in[2];
    float* out = (float*)d_out;

    cudaFuncSetAttribute(fa_mma, cudaFuncAttributeMaxDynamicSharedMemorySize, SMEM_BYTES);

    dim3 grid(SDIM / QT, 4 * 16);   // (16 q-tiles, B*H = 64)
    fa_mma<<<grid, NT, SMEM_BYTES>>>(q, k, v, out);
}

// round 11
// speedup vs baseline: 1.1026x; 1.1026x over previous
#include <cuda_runtime.h>
#include <cstdint>
#include <math.h>

#define SDIM 2048
#define DDIM 64
#define QT 128
#define KT 64
#define NT 128
#define BH 64

#define STR 68   // padded row stride (floats): ldsm 8-row groups hit distinct bank-quads

// smem layout (floats): double-buffered K and Vt, single P
#define OFF_K0 0
#define OFF_K1 (KT*STR)                 // 4352
#define OFF_V0 (2*KT*STR)               // 8704
#define OFF_V1 (3*KT*STR)               // 13056
#define OFF_P  (4*KT*STR)               // 17408
#define BUFSTRIDE (KT*STR)              // 4352 floats between buffers
#define SMEM_FLOATS (OFF_P + QT*STR)    // 26112
#define SMEM_BYTES  (SMEM_FLOATS*4)     // 104448

// pre-rounded K and pre-rounded+transposed V (tf32, RNA)
__device__ float g_kr[(size_t)BH * SDIM * DDIM];
__device__ float g_vt[(size_t)BH * DDIM * SDIM];

__device__ __forceinline__ float tf32r(float x){
    float y; asm("cvt.rna.tf32.f32 %0, %1;" : "=f"(y) : "f"(x)); return y;
}
__device__ __forceinline__ float ex2f(float x){
    float y; asm("ex2.approx.ftz.f32 %0, %1;" : "=f"(y) : "f"(x)); return y;
}
__device__ __forceinline__ uint32_t smem_u32(const void* p){
    uint32_t a;
    asm("{ .reg .u64 t; cvta.to.shared.u64 t, %1; cvt.u32.u64 %0, t; }":"=r"(a):"l"(p));
    return a;
}
__device__ __forceinline__ void mma8(float* d, const float* a, float b0, float b1){
    asm volatile("mma.sync.aligned.m16n8k8.row.col.f32.tf32.tf32.f32 "
                 "{%0,%1,%2,%3},{%4,%5,%6,%7},{%8,%9},{%0,%1,%2,%3};"
                 : "+f"(d[0]),"+f"(d[1]),"+f"(d[2]),"+f"(d[3])
                 : "f"(a[0]),"f"(a[1]),"f"(a[2]),"f"(a[3]),"f"(b0),"f"(b1));
}
__device__ __forceinline__ void ldsm4(uint32_t addr, uint32_t* r){
    asm volatile("ldmatrix.sync.aligned.m8n8.x4.shared.b16 {%0,%1,%2,%3}, [%4];"
                 : "=r"(r[0]),"=r"(r[1]),"=r"(r[2]),"=r"(r[3]) : "r"(addr));
}
__device__ __forceinline__ void cpa16(uint32_t dst, const void* src){
    asm volatile("cp.async.cg.shared.global [%0], [%1], 16;" :: "r"(dst), "l"(src) : "memory");
}
#define CPA_COMMIT() asm volatile("cp.async.commit_group;" ::: "memory")
#define CPA_WAIT(n)  asm volatile("cp.async.wait_group %0;" :: "n"(n) : "memory")

// ---------------- pre-pass: round K to tf32 ----------------
__global__ void __launch_bounds__(256)
prep_k(const float* __restrict__ k)
{
    size_t i = (size_t)blockIdx.x * 256 + threadIdx.x;   // float4 index
    float4 a = ((const float4*)k)[i];
    a.x = tf32r(a.x); a.y = tf32r(a.y); a.z = tf32r(a.z); a.w = tf32r(a.w);
    ((float4*)g_kr)[i] = a;
}

// ---------------- pre-pass: transpose+round V -> g_vt[bh][d][s] ----------------
__global__ void __launch_bounds__(256)
prep_vt(const float* __restrict__ v)
{
    __shared__ float t[32][33];
    const int bh = blockIdx.z;
    const int s0 = blockIdx.x * 32;
    const int d0 = blockIdx.y * 32;
    const int tx = threadIdx.x, ty = threadIdx.y;
    const float* vb = v + (size_t)bh * SDIM * DDIM;
    float* ob = g_vt + (size_t)bh * DDIM * SDIM;
    #pragma unroll
    for (int yy = ty; yy < 32; yy += 8)
        t[yy][tx] = tf32r(vb[(size_t)(s0 + yy) * DDIM + d0 + tx]);
    __syncthreads();
    #pragma unroll
    for (int yy = ty; yy < 32; yy += 8)
        ob[(size_t)(d0 + yy) * SDIM + s0 + tx] = t[tx][yy];
}

// ---------------- main kernel ----------------
__global__ void __launch_bounds__(NT, 2)
fa_mma(const float* __restrict__ qg_, float* __restrict__ og_)
{
    extern __shared__ float sm[];
    float* sP = sm + OFF_P;
    const uint32_t sb = smem_u32(sm);

    const int tid  = threadIdx.x;
    const int wid  = tid >> 5;
    const int lane = tid & 31;
    const int g    = lane >> 2;
    const int q    = lane & 3;
    const int wbase = wid * 32;

    const int bh = blockIdx.y;
    const int qt = blockIdx.x;
    const size_t base = (size_t)bh * SDIM * DDIM;
    const float* qg = qg_ + base + (size_t)qt * QT * DDIM;
    const float* kr = g_kr + base;
    const float* vt = g_vt + base;        // [d][s] layout, same total size
    float*       og = og_ + base + (size_t)qt * QT * DDIM;

    // ---- prologue: issue tile 0 staging (group G0) ----
    {
        #pragma unroll
        for (int it = 0; it < 8; ++it) {
            int c = tid + it * NT, row = c >> 4, c16 = c & 15;
            cpa16(sb + (uint32_t)((OFF_K0 + row * STR + c16 * 4) * 4),
                  kr + row * DDIM + c16 * 4);
        }
        #pragma unroll
        for (int it = 0; it < 8; ++it) {
            int c = tid + it * NT, row = c >> 4, c16 = c & 15;
            cpa16(sb + (uint32_t)((OFF_V0 + row * STR + c16 * 4) * 4),
                  vt + (size_t)row * SDIM + c16 * 4);
        }
        CPA_COMMIT();
    }

    // ---- stage Q into sP (scale*log2e folded, tf32-rounded) ----
    const float qs = 0.125f * 1.44269504088896340736f;
    for (int i = tid; i < QT * DDIM / 4; i += NT) {
        int row = i >> 4, c4 = i & 15;
        float4 a = ((const float4*)qg)[i];
        a.x = tf32r(a.x * qs); a.y = tf32r(a.y * qs);
        a.z = tf32r(a.z * qs); a.w = tf32r(a.w * qs);
        *(float4*)&sP[row * STR + c4 * 4] = a;
    }
    __syncthreads();

    // ---- Q fragments -> registers (persist; m32 = 2 m16 blocks per warp) ----
    float qf[8][2][4];
    #pragma unroll
    for (int kb = 0; kb < 8; ++kb) {
        #pragma unroll
        for (int blk = 0; blk < 2; ++blk) {
            const int r0 = wbase + blk * 16 + g;
            qf[kb][blk][0] = sP[(r0    ) * STR + kb*8 + q    ];
            qf[kb][blk][1] = sP[(r0 + 8) * STR + kb*8 + q    ];
            qf[kb][blk][2] = sP[(r0    ) * STR + kb*8 + q + 4];
            qf[kb][blk][3] = sP[(r0 + 8) * STR + kb*8 + q + 4];
        }
    }
    __syncthreads();

    float o[2][8][4];
    #pragma unroll
    for (int blk = 0; blk < 2; ++blk)
        #pragma unroll
        for (int nb = 0; nb < 8; ++nb)
            { o[blk][nb][0]=0.f; o[blk][nb][1]=0.f; o[blk][nb][2]=0.f; o[blk][nb][3]=0.f; }
    float mx[2][2] = {{-INFINITY,-INFINITY},{-INFINITY,-INFINITY}};
    float lx[2][2] = {{0.f,0.f},{0.f,0.f}};

    // ---- per-lane LDSM base addresses ----
    const int b_nrow = ((lane >> 4) << 3) + (lane & 7);
    const int b_kh   = ((lane >> 3) & 1) << 2;
    const uint32_t aKb0 = sb + (uint32_t)((OFF_K0 + b_nrow * STR + b_kh) * 4);
    const uint32_t aVb0 = sb + (uint32_t)((OFF_V0 + b_nrow * STR + b_kh) * 4);
    const int pa_row = (((lane >> 3) & 1) << 3) + (lane & 7);
    const int pa_kh  = (lane >> 4) << 2;
    const uint32_t aPb = sb + (uint32_t)((OFF_P + (wbase + pa_row) * STR + pa_kh) * 4);

    for (int j = 0; j < SDIM / KT; ++j) {
        // ---- issue next tile's staging, then wait for current ----
        if (j < SDIM / KT - 1) {
            const uint32_t koff = (uint32_t)((OFF_K0 + ((j + 1) & 1) * BUFSTRIDE) * 4);
            const uint32_t voff = (uint32_t)((OFF_V0 + ((j + 1) & 1) * BUFSTRIDE) * 4);
            const float* ks = kr + (size_t)(j + 1) * KT * DDIM;
            const float* vs = vt + (size_t)(j + 1) * KT;
            #pragma unroll
            for (int it = 0; it < 8; ++it) {
                int c = tid + it * NT, row = c >> 4, c16 = c & 15;
                cpa16(sb + koff + (uint32_t)((row * STR + c16 * 4) * 4),
                      ks + row * DDIM + c16 * 4);
            }
            #pragma unroll
            for (int it = 0; it < 8; ++it) {
                int c = tid + it * NT, row = c >> 4, c16 = c & 15;
                cpa16(sb + voff + (uint32_t)((row * STR + c16 * 4) * 4),
                      vs + (size_t)row * SDIM + c16 * 4);
            }
            CPA_COMMIT();
            CPA_WAIT(1);
        } else {
            CPA_WAIT(0);
        }
        __syncthreads();   // all threads' groups for tile j complete & visible

        const uint32_t bufb = (uint32_t)((j & 1) * BUFSTRIDE * 4);
        const uint32_t aKb = aKb0 + bufb;
        const uint32_t aVb = aVb0 + bufb;

        // ---- per 16-row block: S = Q@K^T, online softmax, P -> smem ----
        #pragma unroll
        for (int blk = 0; blk < 2; ++blk) {
            float c[8][4];
            #pragma unroll
            for (int nb = 0; nb < 8; ++nb)
                { c[nb][0]=0.f; c[nb][1]=0.f; c[nb][2]=0.f; c[nb][3]=0.f; }
            #pragma unroll
            for (int kb = 0; kb < 8; ++kb) {
                #pragma unroll
                for (int p = 0; p < 4; ++p) {
                    uint32_t r[4];
                    ldsm4(aKb + (uint32_t)(((p*16) * STR + kb*8) * 4), r);
                    mma8(c[2*p  ], qf[kb][blk], __uint_as_float(r[0]), __uint_as_float(r[1]));
                    mma8(c[2*p+1], qf[kb][blk], __uint_as_float(r[2]), __uint_as_float(r[3]));
                }
            }

            float mtA = -INFINITY, mtB = -INFINITY;
            #pragma unroll
            for (int nb = 0; nb < 8; ++nb) {
                mtA = fmaxf(mtA, fmaxf(c[nb][0], c[nb][1]));
                mtB = fmaxf(mtB, fmaxf(c[nb][2], c[nb][3]));
            }
            mtA = fmaxf(mtA, __shfl_xor_sync(0xffffffffu, mtA, 1));
            mtA = fmaxf(mtA, __shfl_xor_sync(0xffffffffu, mtA, 2));
            mtB = fmaxf(mtB, __shfl_xor_sync(0xffffffffu, mtB, 1));
            mtB = fmaxf(mtB, __shfl_xor_sync(0xffffffffu, mtB, 2));
            const float mnA = fmaxf(mx[blk][0], mtA);
            const float mnB = fmaxf(mx[blk][1], mtB);
            const float aA  = ex2f(mx[blk][0] - mnA);
            const float aB  = ex2f(mx[blk][1] - mnB);
            float lsA = 0.f, lsB = 0.f;
            const int rA = wbase + blk * 16 + g;
            #pragma unroll
            for (int nb = 0; nb < 8; ++nb) {
                float p0 = ex2f(c[nb][0] - mnA);
                float p1 = ex2f(c[nb][1] - mnA);
                float p2 = ex2f(c[nb][2] - mnB);
                float p3 = ex2f(c[nb][3] - mnB);
                lsA += p0 + p1; lsB += p2 + p3;
                float2 fa; fa.x = tf32r(p0); fa.y = tf32r(p1);
                float2 fb; fb.x = tf32r(p2); fb.y = tf32r(p3);
                *(float2*)&sP[(rA    ) * STR + nb*8 + 2*q] = fa;
                *(float2*)&sP[(rA + 8) * STR + nb*8 + 2*q] = fb;
            }
            lsA += __shfl_xor_sync(0xffffffffu, lsA, 1);
            lsA += __shfl_xor_sync(0xffffffffu, lsA, 2);
            lsB += __shfl_xor_sync(0xffffffffu, lsB, 1);
            lsB += __shfl_xor_sync(0xffffffffu, lsB, 2);
            mx[blk][0] = mnA; mx[blk][1] = mnB;
            lx[blk][0] = lx[blk][0] * aA + lsA;
            lx[blk][1] = lx[blk][1] * aB + lsB;
            #pragma unroll
            for (int nb = 0; nb < 8; ++nb) {
                o[blk][nb][0] *= aA; o[blk][nb][1] *= aA;
                o[blk][nb][2] *= aB; o[blk][nb][3] *= aB;
            }
        }
        __syncwarp();   // P stores visible within warp before LDSM reads

        // ---- O += P @ V : A via LDSM from sP, B via LDSM from sVt ----
        #pragma unroll
        for (int kb = 0; kb < 8; ++kb) {
            uint32_t u0[4], u1[4];
            ldsm4(aPb + (uint32_t)((kb*8) * 4), u0);
            ldsm4(aPb + (uint32_t)((16 * STR + kb*8) * 4), u1);
            float a0[4], a1[4];
            #pragma unroll
            for (int t = 0; t < 4; ++t) { a0[t] = __uint_as_float(u0[t]); a1[t] = __uint_as_float(u1[t]); }
            #pragma unroll
            for (int p = 0; p < 4; ++p) {
                uint32_t rv[4];
                ldsm4(aVb + (uint32_t)(((p*16) * STR + kb*8) * 4), rv);
                const float b0 = __uint_as_float(rv[0]);
                const float b1 = __uint_as_float(rv[1]);
                const float b2 = __uint_as_float(rv[2]);
                const float b3 = __uint_as_float(rv[3]);
                mma8(o[0][2*p  ], a0, b0, b1);
                mma8(o[0][2*p+1], a0, b2, b3);
                mma8(o[1][2*p  ], a1, b0, b1);
                mma8(o[1][2*p+1], a1, b2, b3);
            }
        }
        __syncthreads();   // tile j reads done before next iter's cp.async overwrites
    }

    // ---- epilogue: normalize, store ----
    #pragma unroll
    for (int blk = 0; blk < 2; ++blk) {
        const float invA = 1.0f / lx[blk][0];
        const float invB = 1.0f / lx[blk][1];
        const int rA = wbase + blk * 16 + g;
        #pragma unroll
        for (int nb = 0; nb < 8; ++nb) {
            float2 sa; sa.x = o[blk][nb][0] * invA; sa.y = o[blk][nb][1] * invA;
            float2 sb2; sb2.x = o[blk][nb][2] * invB; sb2.y = o[blk][nb][3] * invB;
            *(float2*)&og[(size_t)(rA    ) * DDIM + nb*8 + 2*q] = sa;
            *(float2*)&og[(size_t)(rA + 8) * DDIM + nb*8 + 2*q] = sb2;
        }
    }
}

extern "C" void kernel_launch(void* const* d_in, const int* in_sizes, int n_in,
                              void* d_out, int out_size)
{
    const float* q = (const float*)d_in[0];
    const float* k = (const float*)d_in[1];
    const float* v = (const float*)d_in[2];
    float* out = (float*)d_out;

    cudaFuncSetAttribute(fa_mma, cudaFuncAttributeMaxDynamicSharedMemorySize, SMEM_BYTES);

    // pre-pass: round K, transpose+round V
    prep_k<<<(BH * SDIM * DDIM / 4) / 256, 256>>>(k);
    prep_vt<<<dim3(SDIM / 32, DDIM / 32, BH), dim3(32, 8)>>>(v);

    dim3 grid(SDIM / QT, BH);   // (16 q-tiles, B*H = 64)
    fa_mma<<<grid, NT, SMEM_BYTES>>>(q, out);
}